// round 17
// baseline (speedup 1.0000x reference)
#include <cuda_runtime.h>
#include <cuda_bf16.h>

// ---------------- problem constants (from reference setup_inputs) ----------------
constexpr int B = 64;
constexpr int P = 24576;
constexpr int C = 81;            // NUM_CLASSES + 1
constexpr int NEG_POS_RATIO = 3;

constexpr int TPB = 96;                  // threads per block (3 warps)
constexpr int APB = 48;                  // anchors per tile (2 lanes/anchor pair-split)
constexpr int NT  = (B * P) / APB;       // 32768 tiles
constexpr int TPI = P / APB;             // 512 tiles per image (tiles never straddle images)
constexpr int TILE_F  = APB * C;         // 3888 floats per tile (15552 B)
constexpr int TILE_F4 = TILE_F / 4;      // 972 float4
constexpr int NBLK = 1036;               // persistent CTAs: 148 SMs x 7
constexpr int NW   = TPB / 32;           // 3 warps -> 3 partial slots per tile

// ---------------- scratch (device globals; no allocation allowed) ----------------
__device__ float g_ce_neg[B * P];   // scratch for fallback path ONLY (filled on demand)
__device__ float g_pos[NT * NW];    // per-warp-per-tile positive loss  [distinct addrs]
__device__ float g_negp[NT * NW];   // per-warp-per-tile negative-CE sum
__device__ int   g_cnt[NT * NW];    // per-warp-per-tile positive counts
__device__ float g_img_loss[B];
__device__ int   g_img_pos[B];
__device__ int   g_done;            // phase-1 arrival ticket (reset each run)
__device__ int   g_done2;           // phase-2 arrival ticket (reset each run)

// ---------------- helpers ----------------
__device__ __forceinline__ float huber1(float d) {
    float ad = fabsf(d);
    return ad < 1.0f ? 0.5f * d * d : ad - 0.5f;
}
__device__ __forceinline__ void cp_async16(void* smem_dst, const void* gmem_src) {
    unsigned sa = (unsigned)__cvta_generic_to_shared(smem_dst);
    asm volatile("cp.async.cg.shared.global [%0], [%1], 16;" :: "r"(sa), "l"(gmem_src));
}
__device__ __forceinline__ void cp_commit() { asm volatile("cp.async.commit_group;"); }
__device__ __forceinline__ void cp_wait1()  { asm volatile("cp.async.wait_group 1;"); }

// ---------------- single persistent kernel -----------------------------------------
__global__ void __launch_bounds__(TPB, 7) k_ssd(
    const float* __restrict__ loc_preds,
    const float* __restrict__ cls_preds,
    const float* __restrict__ loc_targets,
    const int*   __restrict__ cls_targets,
    float* __restrict__ out)
{
    __shared__ float buf[2][TILE_F];     // 2 x 15552 B
    __shared__ int   s_tgt[2][APB];
    __shared__ float swf1[NW], swf2[NW]; // per-warp reduction slots
    __shared__ int   swi1[NW];
    __shared__ float sb_f1, sb_f2;       // block broadcasts
    __shared__ int   sb_i1;
    __shared__ unsigned s_bits;
    __shared__ int   s_last;

    const int tid  = threadIdx.x;
    const int lane = tid & 31;
    const int wid  = tid >> 5;
    const int pr   = tid >> 1;           // anchor within tile (pair index, 0..47)
    const int odd  = tid & 1;            // class-half: even -> [0,41), odd -> [41,81)
    const int base = odd * 41;

    auto stage = [&](int tile, int s) {
        const float4* __restrict__ src =
            reinterpret_cast<const float4*>(cls_preds + (long)tile * TILE_F);
        float4* dst = reinterpret_cast<float4*>(buf[s]);
        #pragma unroll
        for (int it = 0; it < 10; it++)            // 10 rounds: 960 float4
            cp_async16(&dst[tid + it * TPB], &src[tid + it * TPB]);
        if (tid < TILE_F4 - 10 * TPB)              // 12-thread tail
            cp_async16(&dst[tid + 10 * TPB], &src[tid + 10 * TPB]);
        else if (tid >= 84) {                      // 12 threads stage targets (48 ints)
            int i = tid - 84;
            const int4* ts = reinterpret_cast<const int4*>(cls_targets + (long)tile * APB);
            cp_async16(&reinterpret_cast<int4*>(s_tgt[s])[i], &ts[i]);
        }
    };

    int tile = blockIdx.x;
    if (tile < NT) stage(tile, 0);
    cp_commit();

    int cur = 0;
    for (; tile < NT; tile += NBLK) {
        const int nxt = tile + NBLK;
        if (nxt < NT) stage(nxt, cur ^ 1);
        cp_commit();
        cp_wait1();
        __syncthreads();                            // tile resident

        const long ag = (long)tile * APB + pr;
        const int t = s_tgt[cur][pr];

        float4 lp, lt;
        if (!odd) {
            lp = reinterpret_cast<const float4*>(loc_preds)[ag];
            lt = reinterpret_cast<const float4*>(loc_targets)[ag];
        }

        // half-row exp sums; lane-uniform loop (base differs per lane, no divergence)
        const float* __restrict__ row = buf[cur] + pr * C;
        float e0 = 0.0f, e1 = 0.0f;
        #pragma unroll
        for (int i = 0; i < 40; i += 2) {
            e0 += __expf(row[base + i]);
            e1 += __expf(row[base + i + 1]);
        }
        if (!odd) e0 += __expf(row[40]);            // even half has 41 classes
        float e = e0 + e1;
        e += __shfl_xor_sync(0xFFFFFFFFu, e, 1);    // combine pair halves

        const bool own = (odd == (t > 40));
        float cand = own ? row[t] : 0.0f;
        const float xt = cand + __shfl_xor_sync(0xFFFFFFFFu, cand, 1);

        const float ce = __logf(e) - xt;

        float accp = 0.0f, accn = 0.0f;
        int cnt = 0;
        if (!odd) {                                  // even lane owns the anchor's result
            const bool pos = (t > 0);
            if (pos) {
                accp = ce + huber1(lp.x - lt.x) + huber1(lp.y - lt.y) +
                            huber1(lp.z - lt.z) + huber1(lp.w - lt.w);
                cnt = 1;
            } else {
                accn = ce;
            }
        }
        #pragma unroll
        for (int o = 16; o; o >>= 1) {
            accp += __shfl_down_sync(0xFFFFFFFFu, accp, o);
            accn += __shfl_down_sync(0xFFFFFFFFu, accn, o);
            cnt  += __shfl_down_sync(0xFFFFFFFFu, cnt,  o);
        }
        if (lane == 0) {                             // distinct addresses: plain stores
            g_pos[tile * NW + wid]  = accp;
            g_negp[tile * NW + wid] = accn;
            g_cnt[tile * NW + wid]  = cnt;
        }
        __syncthreads();                             // buf[cur] free before next stage
        cur ^= 1;
    }

    // ---- phase-1 ticket: all CTAs announce completion ----
    if (tid == 0) {
        __threadfence();
        atomicAdd(&g_done, 1);
    }
    if (blockIdx.x >= B) return;                     // only CTAs 0..63 continue

    // ---- deadlock-free poll: 64 spinning CTAs << resident capacity, so any
    //      not-yet-placed CTA always finds a free slot and can finish ----
    if (tid == 0) {
        while (atomicAdd(&g_done, 0) < NBLK) { }
        __threadfence();
    }
    __syncthreads();

    // ================= per-image epilogue: CTA b handles image b =================
    const int b = blockIdx.x;

    // reduce this image's per-warp-per-tile partials (L2-hot)
    {
        float p = 0.0f, n = 0.0f; int c = 0;
        for (int i = tid; i < TPI * NW; i += TPB) {  // 16 iterations
            int idx = b * TPI * NW + i;
            p += g_pos[idx]; n += g_negp[idx]; c += g_cnt[idx];
        }
        #pragma unroll
        for (int o = 16; o; o >>= 1) {
            p += __shfl_down_sync(0xFFFFFFFFu, p, o);
            n += __shfl_down_sync(0xFFFFFFFFu, n, o);
            c += __shfl_down_sync(0xFFFFFFFFu, c, o);
        }
        if (lane == 0) { swf1[wid] = p; swf2[wid] = n; swi1[wid] = c; }
        __syncthreads();
        if (tid == 0) {
            sb_f1 = swf1[0] + swf1[1] + swf1[2];
            sb_f2 = swf2[0] + swf2[1] + swf2[2];
            sb_i1 = swi1[0] + swi1[1] + swi1[2];
        }
        __syncthreads();
    }
    const float pos_loss = sb_f1;
    float neg = sb_f2;
    const int np = sb_i1;
    __syncthreads();

    const long negc = (long)P - np;
    const long k = min((long)NEG_POS_RATIO * (long)np, negc);

    if (k < negc) {   // general path (not taken on this data); exact tie-corrected top-k
        float* row = g_ce_neg + (size_t)b * P;
        if (k <= 0) {
            neg = 0.0f;
        } else {
            // recompute this image's CE values into scratch (fallback only;
            // same formula as the hot loop so results are identical)
            const float* __restrict__ cp = cls_preds + (size_t)b * P * C;
            const int*   __restrict__ ct = cls_targets + (size_t)b * P;
            for (int i = tid; i < P; i += TPB) {
                const float* r = cp + (size_t)i * C;
                float s0 = 0.0f, s1 = 0.0f;
                #pragma unroll
                for (int cc = 0; cc < 80; cc += 2) { s0 += __expf(r[cc]); s1 += __expf(r[cc + 1]); }
                s0 += __expf(r[80]);
                const int t = ct[i];
                const float ce = __logf(s0 + s1) - r[t];
                row[i] = (t > 0) ? 0.0f : ce;
            }
            __syncthreads();

            // block max
            float m = 0.0f;
            for (int i = tid; i < P; i += TPB) m = fmaxf(m, row[i]);
            #pragma unroll
            for (int o = 16; o; o >>= 1) m = fmaxf(m, __shfl_down_sync(0xFFFFFFFFu, m, o));
            if (lane == 0) swf1[wid] = m;
            __syncthreads();
            if (tid == 0) sb_f1 = fmaxf(swf1[0], fmaxf(swf1[1], swf1[2]));
            __syncthreads();
            m = sb_f1;

            unsigned lo = 0u, hi = __float_as_uint(fmaxf(m, 0.0f));
            while (lo < hi) {
                unsigned mid = lo + ((hi - lo + 1u) >> 1);
                float thr = __uint_as_float(mid);
                int cc = 0;
                for (int i = tid; i < P; i += TPB) cc += (row[i] >= thr);
                #pragma unroll
                for (int o = 16; o; o >>= 1) cc += __shfl_down_sync(0xFFFFFFFFu, cc, o);
                if (lane == 0) swi1[wid] = cc;
                __syncthreads();
                if (tid == 0) sb_i1 = swi1[0] + swi1[1] + swi1[2];
                __syncthreads();
                int cge = sb_i1;
                __syncthreads();
                if ((long)cge >= k) lo = mid; else hi = mid - 1u;
            }
            if (tid == 0) s_bits = lo;
            __syncthreads();
            float thr = __uint_as_float(s_bits);

            float sg = 0.0f; int cg = 0;
            for (int i = tid; i < P; i += TPB) {
                float v = row[i];
                if (v > thr) { sg += v; cg++; }
            }
            #pragma unroll
            for (int o = 16; o; o >>= 1) {
                sg += __shfl_down_sync(0xFFFFFFFFu, sg, o);
                cg += __shfl_down_sync(0xFFFFFFFFu, cg, o);
            }
            if (lane == 0) { swf1[wid] = sg; swi1[wid] = cg; }
            __syncthreads();
            if (tid == 0) {
                sb_f1 = swf1[0] + swf1[1] + swf1[2];
                sb_i1 = swi1[0] + swi1[1] + swi1[2];
            }
            __syncthreads();
            neg = sb_f1 + (float)(k - (long)sb_i1) * thr;
            __syncthreads();
        }
    }

    // ---- publish; phase-2 ticket elects the final combiner ----
    if (tid == 0) {
        g_img_loss[b] = pos_loss + neg;
        g_img_pos[b] = np;
        __threadfence();
        int t2 = atomicAdd(&g_done2, 1);
        s_last = (t2 == B - 1) ? 1 : 0;
    }
    __syncthreads();
    if (!s_last) return;

    // all 64 epilogue CTAs have published: combine, write scalar, reset tickets.
    {
        float ls = 0.0f; int lc = 0;
        if (tid < B) { ls = g_img_loss[tid]; lc = g_img_pos[tid]; }
        #pragma unroll
        for (int o = 16; o; o >>= 1) {
            ls += __shfl_down_sync(0xFFFFFFFFu, ls, o);
            lc += __shfl_down_sync(0xFFFFFFFFu, lc, o);
        }
        if (lane == 0) { swf1[wid] = ls; swi1[wid] = lc; }
        __syncthreads();
        if (tid == 0) {
            float tot = swf1[0] + swf1[1] + swf1[2];
            int np_all = swi1[0] + swi1[1] + swi1[2];
            float N = (float)(np_all > 0 ? np_all : 1);
            out[0] = tot / N;
            atomicExch(&g_done, 0);
            atomicExch(&g_done2, 0);
        }
    }
}

// ---------------- launch ----------------
extern "C" void kernel_launch(void* const* d_in, const int* in_sizes, int n_in,
                              void* d_out, int out_size) {
    const float* loc_preds   = (const float*)d_in[0];
    const float* cls_preds   = (const float*)d_in[1];
    const float* loc_targets = (const float*)d_in[2];
    const int*   cls_targets = (const int*)d_in[3];
    float* out = (float*)d_out;

    k_ssd<<<NBLK, TPB>>>(loc_preds, cls_preds, loc_targets, cls_targets, out);
}